// round 9
// baseline (speedup 1.0000x reference)
#include <cuda_runtime.h>
#include <cuda_bf16.h>
#include <cstdint>
#include <math.h>

#define NB 2
#define NS 1024
#define ND 1024
#define NH 16
#define NHD 64
#define NTOK (NB*NS)
#define EPSF 1e-6f
#define PADR 68
#define KS 20   // u32 stride of smem tile rows (conflict-free: g*20+t distinct mod 32)

// ---------------- scratch (static device memory; no allocs) ----------------
struct Scratch {
    float qm[NTOK*ND];
    float km[NTOK*ND];
    float vm[NTOK*ND];
    float vvar[NTOK*ND];
    float ym[NTOK*ND];
    float T[NTOK*ND];
    float cpart[NB*8*ND];
    float csum[NB*ND];
    // bf16 hi/lo splits of X operands
    __nv_bfloat16 xqh[NTOK*ND], xql[NTOK*ND];
    __nv_bfloat16 xkh[NTOK*ND], xkl[NTOK*ND];
    __nv_bfloat16 xvh[NTOK*ND], xvl[NTOK*ND];
    __nv_bfloat16 xsh[NTOK*ND], xsl[NTOK*ND];   // v_scale^2
    __nv_bfloat16 xyh[NTOK*ND], xyl[NTOK*ND];   // ym
    __nv_bfloat16 xth[NTOK*ND], xtl[NTOK*ND];   // T
    // bf16 hi/lo splits of W operands
    __nv_bfloat16 wqh[ND*ND], wql[ND*ND];
    __nv_bfloat16 wkh[ND*ND], wkl[ND*ND];
    __nv_bfloat16 wvh[ND*ND], wvl[ND*ND];
    __nv_bfloat16 w2h[ND*ND], w2l[ND*ND];       // Wv^2
    __nv_bfloat16 woh[ND*ND], wol[ND*ND];
    __nv_bfloat16 o2h[ND*ND], o2l[ND*ND];       // Wo^2
};
__device__ Scratch g_s;

static inline __nv_bfloat162* BF2(__nv_bfloat16* p) { return (__nv_bfloat162*)p; }

// ---------------- warp-level bf16 MMA (sm_80 baseline ISA) -----------------
__device__ __forceinline__ void mma_bf16(float* c, const uint32_t* a, const uint32_t* b) {
    asm volatile(
        "mma.sync.aligned.m16n8k16.row.col.f32.bf16.bf16.f32 "
        "{%0,%1,%2,%3}, {%4,%5,%6,%7}, {%8,%9}, {%0,%1,%2,%3};\n"
        : "+f"(c[0]), "+f"(c[1]), "+f"(c[2]), "+f"(c[3])
        : "r"(a[0]), "r"(a[1]), "r"(a[2]), "r"(a[3]), "r"(b[0]), "r"(b[1]));
}

// ---------------- fp32 -> bf16 hi/lo split (optionally squared) -------------
__global__ void split_bf16(const float* __restrict__ x,
                           __nv_bfloat162* __restrict__ hi,
                           __nv_bfloat162* __restrict__ lo,
                           int n4, int sq) {
    int i = blockIdx.x * blockDim.x + threadIdx.x;
    if (i >= n4) return;
    float4 v = ((const float4*)x)[i];
    if (sq) { v.x *= v.x; v.y *= v.y; v.z *= v.z; v.w *= v.w; }
    __nv_bfloat162 h0 = __floats2bfloat162_rn(v.x, v.y);
    __nv_bfloat162 h1 = __floats2bfloat162_rn(v.z, v.w);
    __nv_bfloat162 l0 = __floats2bfloat162_rn(v.x - __low2float(h0), v.y - __high2float(h0));
    __nv_bfloat162 l1 = __floats2bfloat162_rn(v.z - __low2float(h1), v.w - __high2float(h1));
    hi[i * 2]     = h0;
    hi[i * 2 + 1] = h1;
    lo[i * 2]     = l0;
    lo[i * 2 + 1] = l1;
}

// ---------------- split-bf16 NT GEMM on mma.sync ----------------------------
// Y[row,col] = f( sum_k X[row,k]*W[col,k] ), X=Xh+Xl, W=Wh+Wl (HH+HL+LH terms)
// MODE 0: +bias ; MODE 1: (sqrt(v)+eps)^2 ; MODE 2: sqrt(v)
template<int MODE>
__global__ void __launch_bounds__(256) gemm_mma(
    const __nv_bfloat16* __restrict__ Xh, const __nv_bfloat16* __restrict__ Xl,
    const __nv_bfloat16* __restrict__ Wh, const __nv_bfloat16* __restrict__ Wl,
    const float* __restrict__ bias, float* __restrict__ Y) {

    __shared__ uint32_t SH[4][128 * KS];    // Xh, Xl, Wh, Wl tiles (k32 chunk, paired bf16)

    const int tid = threadIdx.x;
    const int wid = tid >> 5, lane = tid & 31;
    const int g = lane >> 2, tig = lane & 3;          // mma fragment coords
    const int wm = wid & 1, wn = wid >> 1;            // 2x4 warp grid
    const int col0 = blockIdx.x * 128, row0 = blockIdx.y * 128;

    const __nv_bfloat16* srcs[4];
    srcs[0] = Xh + (size_t)row0 * ND;
    srcs[1] = Xl + (size_t)row0 * ND;
    srcs[2] = Wh + (size_t)col0 * ND;
    srcs[3] = Wl + (size_t)col0 * ND;

    float acc[4][4][4] = {};                          // [mi][ni][frag]

    for (int c = 0; c < 32; ++c) {                    // K chunks of 32
        const int k0 = c * 32;
        if (c) __syncthreads();
        #pragma unroll
        for (int a = 0; a < 4; ++a) {
            #pragma unroll
            for (int i = 0; i < 2; ++i) {
                int v = tid + i * 256;                // 0..511
                int row = v >> 2, quad = v & 3;
                uint4 val = *(const uint4*)(srcs[a] + (size_t)row * ND + k0 + quad * 8);
                *(uint4*)&SH[a][row * KS + quad * 4] = val;
            }
        }
        __syncthreads();

        #pragma unroll
        for (int s = 0; s < 2; ++s) {                 // two k16 steps
            const int s8 = s * 8;
            uint32_t ah[4][4], al[4][4], bh[4][2], bl[4][2];
            #pragma unroll
            for (int mi = 0; mi < 4; ++mi) {
                int r0 = (wm * 64 + mi * 16 + g) * KS + s8 + tig;
                int r1 = r0 + 8 * KS;
                ah[mi][0] = SH[0][r0];     ah[mi][1] = SH[0][r1];
                ah[mi][2] = SH[0][r0 + 4]; ah[mi][3] = SH[0][r1 + 4];
                al[mi][0] = SH[1][r0];     al[mi][1] = SH[1][r1];
                al[mi][2] = SH[1][r0 + 4]; al[mi][3] = SH[1][r1 + 4];
            }
            #pragma unroll
            for (int ni = 0; ni < 4; ++ni) {
                int n0 = (wn * 32 + ni * 8 + g) * KS + s8 + tig;
                bh[ni][0] = SH[2][n0]; bh[ni][1] = SH[2][n0 + 4];
                bl[ni][0] = SH[3][n0]; bl[ni][1] = SH[3][n0 + 4];
            }
            #pragma unroll
            for (int mi = 0; mi < 4; ++mi)
                #pragma unroll
                for (int ni = 0; ni < 4; ++ni) {
                    mma_bf16(acc[mi][ni], ah[mi], bh[ni]);
                    mma_bf16(acc[mi][ni], ah[mi], bl[ni]);
                    mma_bf16(acc[mi][ni], al[mi], bh[ni]);
                }
        }
    }

    // epilogue
    #pragma unroll
    for (int mi = 0; mi < 4; ++mi) {
        const int rA = row0 + wm * 64 + mi * 16 + g;
        #pragma unroll
        for (int ni = 0; ni < 4; ++ni) {
            const int cA = col0 + wn * 32 + ni * 8 + tig * 2;
            float v0 = acc[mi][ni][0], v1 = acc[mi][ni][1];
            float v2 = acc[mi][ni][2], v3 = acc[mi][ni][3];
            if (MODE == 0) {
                float b0 = bias[cA], b1 = bias[cA + 1];
                v0 += b0; v1 += b1; v2 += b0; v3 += b1;
            }
            if (MODE == 1) {
                float s;
                s = sqrtf(fmaxf(v0, 0.f)) + EPSF; v0 = s * s;
                s = sqrtf(fmaxf(v1, 0.f)) + EPSF; v1 = s * s;
                s = sqrtf(fmaxf(v2, 0.f)) + EPSF; v2 = s * s;
                s = sqrtf(fmaxf(v3, 0.f)) + EPSF; v3 = s * s;
            }
            if (MODE == 2) {
                v0 = sqrtf(fmaxf(v0, 0.f)); v1 = sqrtf(fmaxf(v1, 0.f));
                v2 = sqrtf(fmaxf(v2, 0.f)); v3 = sqrtf(fmaxf(v3, 0.f));
            }
            *(float2*)&Y[(size_t)rA * ND + cA]       = make_float2(v0, v1);
            *(float2*)&Y[(size_t)(rA + 8) * ND + cA] = make_float2(v2, v3);
        }
    }
}

// ---------------- column sums of vvar over S: csum[b][d] -------------------
__global__ void colsum_part(const float* __restrict__ vvar, float* __restrict__ cpart) {
    int d = blockIdx.x * 256 + threadIdx.x;
    int chunk = blockIdx.y;
    int b = blockIdx.z;
    const float* p = vvar + ((size_t)b * NS + chunk * 128) * ND + d;
    float s = 0.f;
    #pragma unroll 8
    for (int t = 0; t < 128; ++t) s += p[(size_t)t * ND];
    cpart[(b * 8 + chunk) * ND + d] = s;
}

__global__ void colsum_final(const float* __restrict__ cpart, float* __restrict__ csum) {
    int idx = blockIdx.x * 256 + threadIdx.x;
    int b = idx / ND, d = idx % ND;
    float s = 0.f;
    #pragma unroll
    for (int c = 0; c < 8; ++c) s += cpart[(b * 8 + c) * ND + d];
    csum[idx] = s;
}

// ---------------- fused distributional attention ---------------------------
#define ATTN_SMEM_FLOATS (6*64*PADR + 3*64 + 64*16)
__global__ void __launch_bounds__(256, 2) attn_kernel(
    const float* __restrict__ qm, const float* __restrict__ km,
    const float* __restrict__ vm, const float* __restrict__ vvar,
    const float* __restrict__ csum, const float* __restrict__ tau_p,
    float* __restrict__ ym, float* __restrict__ Tout) {

    extern __shared__ float smem[];
    float* QT  = smem;
    float* KT  = QT  + 64 * PADR;
    float* Vs  = KT  + 64 * PADR;
    float* VVs = Vs  + 64 * PADR;
    float* PT1 = VVs + 64 * PADR;
    float* PT2 = PT1 + 64 * PADR;
    float* rowmax = PT2 + 64 * PADR;
    float* rowz1  = rowmax + 64;
    float* rowz2  = rowz1 + 64;
    float* red    = rowz2 + 64;

    const int tid = threadIdx.x;
    const int tx = tid & 15, ty = tid >> 4;
    const int q0 = blockIdx.x * 64;
    const int h  = blockIdx.y;
    const int b  = blockIdx.z;

    const float tau   = tau_p[0];
    const float scl   = 1.0f / (8.0f * tau);
    const float s_var = (0.1f + EPSF) / 64.0f + EPSF;
    const float l_var = s_var / (tau * tau) + EPSF;
    const float cc    = rsqrtf(1.0f + 0.39269908169872414f * l_var);

    const size_t hoff = (size_t)h * NHD;
    const float* qbase = qm + ((size_t)b * NS + q0) * ND + hoff;

    for (int idx = tid; idx < 64 * 64; idx += 256) {
        int d = idx & 63, r = idx >> 6;
        QT[d * PADR + r] = qbase[(size_t)r * ND + d] * scl;
    }

    float lm[4] = {-INFINITY, -INFINITY, -INFINITY, -INFINITY};
    for (int kt = 0; kt < 16; ++kt) {
        __syncthreads();
        const float* kbase = km + ((size_t)b * NS + kt * 64) * ND + hoff;
        for (int idx = tid; idx < 64 * 64; idx += 256) {
            int d = idx & 63, r = idx >> 6;
            KT[d * PADR + r] = kbase[(size_t)r * ND + d];
        }
        __syncthreads();
        float sc[4][4] = {};
        #pragma unroll 8
        for (int d = 0; d < 64; ++d) {
            float4 qa = *(const float4*)&QT[d * PADR + ty * 4];
            float4 kb = *(const float4*)&KT[d * PADR + tx * 4];
            float av[4] = {qa.x, qa.y, qa.z, qa.w};
            float bv[4] = {kb.x, kb.y, kb.z, kb.w};
            #pragma unroll
            for (int i = 0; i < 4; ++i)
                #pragma unroll
                for (int j = 0; j < 4; ++j)
                    sc[i][j] = fmaf(av[i], bv[j], sc[i][j]);
        }
        #pragma unroll
        for (int i = 0; i < 4; ++i)
            #pragma unroll
            for (int j = 0; j < 4; ++j)
                lm[i] = fmaxf(lm[i], sc[i][j]);
    }
    __syncthreads();
    #pragma unroll
    for (int i = 0; i < 4; ++i) red[(ty * 4 + i) * 16 + tx] = lm[i];
    __syncthreads();
    if (tid < 64) {
        float m = red[tid * 16];
        #pragma unroll
        for (int t = 1; t < 16; ++t) m = fmaxf(m, red[tid * 16 + t]);
        rowmax[tid] = m;
    }
    __syncthreads();

    float mrow[4];
    #pragma unroll
    for (int i = 0; i < 4; ++i) mrow[i] = rowmax[ty * 4 + i];

    float acc1[4][4] = {}, acc2[4][4] = {}, acc3[4][4] = {}, acc4[4][4] = {};
    float z1l[4] = {}, z2l[4] = {};
    for (int kt = 0; kt < 16; ++kt) {
        __syncthreads();
        const float* kbase  = km   + ((size_t)b * NS + kt * 64) * ND + hoff;
        const float* vbase  = vm   + ((size_t)b * NS + kt * 64) * ND + hoff;
        const float* vvbase = vvar + ((size_t)b * NS + kt * 64) * ND + hoff;
        for (int idx = tid; idx < 64 * 64; idx += 256) {
            int d = idx & 63, r = idx >> 6;
            KT[d * PADR + r]  = kbase[(size_t)r * ND + d];
            Vs[r * PADR + d]  = vbase[(size_t)r * ND + d];
            VVs[r * PADR + d] = vvbase[(size_t)r * ND + d];
        }
        __syncthreads();

        float sc[4][4] = {};
        #pragma unroll 8
        for (int d = 0; d < 64; ++d) {
            float4 qa = *(const float4*)&QT[d * PADR + ty * 4];
            float4 kb = *(const float4*)&KT[d * PADR + tx * 4];
            float av[4] = {qa.x, qa.y, qa.z, qa.w};
            float bv[4] = {kb.x, kb.y, kb.z, kb.w};
            #pragma unroll
            for (int i = 0; i < 4; ++i)
                #pragma unroll
                for (int j = 0; j < 4; ++j)
                    sc[i][j] = fmaf(av[i], bv[j], sc[i][j]);
        }
        #pragma unroll
        for (int i = 0; i < 4; ++i) {
            #pragma unroll
            for (int j = 0; j < 4; ++j) {
                float dlt = sc[i][j] - mrow[i];
                float e1 = expf(dlt);
                float e2 = expf(cc * dlt);
                PT1[(tx * 4 + j) * PADR + ty * 4 + i] = e1;
                PT2[(tx * 4 + j) * PADR + ty * 4 + i] = e2;
                z1l[i] += e1;
                z2l[i] += e2;
            }
        }
        __syncthreads();

        #pragma unroll 4
        for (int t = 0; t < 64; ++t) {
            float4 p1 = *(const float4*)&PT1[t * PADR + ty * 4];
            float4 p2 = *(const float4*)&PT2[t * PADR + ty * 4];
            float4 vv = *(const float4*)&Vs[t * PADR + tx * 4];
            float4 wv = *(const float4*)&VVs[t * PADR + tx * 4];
            float p1a[4] = {p1.x, p1.y, p1.z, p1.w};
            float p2a[4] = {p2.x, p2.y, p2.z, p2.w};
            float va[4]  = {vv.x, vv.y, vv.z, vv.w};
            float wa[4]  = {wv.x, wv.y, wv.z, wv.w};
            #pragma unroll
            for (int i = 0; i < 4; ++i) {
                float p2s = p2a[i] * p2a[i];
                #pragma unroll
                for (int j = 0; j < 4; ++j) {
                    acc1[i][j] = fmaf(p1a[i], va[j], acc1[i][j]);
                    acc2[i][j] = fmaf(p2a[i], va[j], acc2[i][j]);
                    acc3[i][j] = fmaf(p2a[i], wa[j], acc3[i][j]);
                    acc4[i][j] = fmaf(p2s,   wa[j], acc4[i][j]);
                }
            }
        }
    }

    __syncthreads();
    #pragma unroll
    for (int i = 0; i < 4; ++i) red[(ty * 4 + i) * 16 + tx] = z1l[i];
    __syncthreads();
    if (tid < 64) {
        float s = 0.f;
        #pragma unroll
        for (int t = 0; t < 16; ++t) s += red[tid * 16 + t];
        rowz1[tid] = s;
    }
    __syncthreads();
    #pragma unroll
    for (int i = 0; i < 4; ++i) red[(ty * 4 + i) * 16 + tx] = z2l[i];
    __syncthreads();
    if (tid < 64) {
        float s = 0.f;
        #pragma unroll
        for (int t = 0; t < 16; ++t) s += red[tid * 16 + t];
        rowz2[tid] = s;
    }
    __syncthreads();

    const float Aconst = 1e-4f + EPSF;
    #pragma unroll
    for (int i = 0; i < 4; ++i) {
        int r = ty * 4 + i;
        float iZ1 = 1.0f / rowz1[r];
        float iZ2 = 1.0f / rowz2[r];
        float o1[4], o2[4];
        #pragma unroll
        for (int j = 0; j < 4; ++j) {
            int dc = tx * 4 + j;
            float ymu = acc1[i][j] * iZ1 + acc2[i][j] * iZ2;
            float yv  = Aconst * csum[b * ND + (int)hoff + dc]
                      + l_var * (acc3[i][j] * iZ2 - acc4[i][j] * iZ2 * iZ2);
            float ys = sqrtf(yv + EPSF) + EPSF;
            o1[j] = ymu;
            o2[j] = ys * ys;
        }
        size_t off = ((size_t)b * NS + q0 + r) * ND + hoff + tx * 4;
        *(float4*)&ym[off]   = make_float4(o1[0], o1[1], o1[2], o1[3]);
        *(float4*)&Tout[off] = make_float4(o2[0], o2[1], o2[2], o2[3]);
    }
}

// ---------------- launch ----------------------------------------------------
extern "C" void kernel_launch(void* const* d_in, const int* in_sizes, int n_in,
                              void* d_out, int out_size) {
    (void)in_sizes; (void)n_in; (void)out_size;
    const float* q_loc   = (const float*)d_in[0];
    const float* k_loc   = (const float*)d_in[2];
    const float* v_loc   = (const float*)d_in[4];
    const float* v_scale = (const float*)d_in[5];
    const float* Wq = (const float*)d_in[6];
    const float* bq = (const float*)d_in[7];
    const float* Wk = (const float*)d_in[8];
    const float* bk = (const float*)d_in[9];
    const float* Wv = (const float*)d_in[10];
    const float* bv = (const float*)d_in[11];
    const float* Wo = (const float*)d_in[12];
    const float* bo = (const float*)d_in[13];
    const float* tau = (const float*)d_in[14];
    float* out = (float*)d_out;

    Scratch* sp = nullptr;
    cudaGetSymbolAddress((void**)&sp, g_s);

    const int attn_smem = ATTN_SMEM_FLOATS * (int)sizeof(float);
    cudaFuncSetAttribute(attn_kernel, cudaFuncAttributeMaxDynamicSharedMemorySize, attn_smem);

    const int n4x = NTOK * ND / 4, n4w = ND * ND / 4;
    // W splits
    split_bf16<<<n4w/256, 256>>>(Wq, BF2(sp->wqh), BF2(sp->wql), n4w, 0);
    split_bf16<<<n4w/256, 256>>>(Wk, BF2(sp->wkh), BF2(sp->wkl), n4w, 0);
    split_bf16<<<n4w/256, 256>>>(Wv, BF2(sp->wvh), BF2(sp->wvl), n4w, 0);
    split_bf16<<<n4w/256, 256>>>(Wv, BF2(sp->w2h), BF2(sp->w2l), n4w, 1);
    split_bf16<<<n4w/256, 256>>>(Wo, BF2(sp->woh), BF2(sp->wol), n4w, 0);
    split_bf16<<<n4w/256, 256>>>(Wo, BF2(sp->o2h), BF2(sp->o2l), n4w, 1);
    // X splits
    split_bf16<<<n4x/256, 256>>>(q_loc,   BF2(sp->xqh), BF2(sp->xql), n4x, 0);
    split_bf16<<<n4x/256, 256>>>(k_loc,   BF2(sp->xkh), BF2(sp->xkl), n4x, 0);
    split_bf16<<<n4x/256, 256>>>(v_loc,   BF2(sp->xvh), BF2(sp->xvl), n4x, 0);
    split_bf16<<<n4x/256, 256>>>(v_scale, BF2(sp->xsh), BF2(sp->xsl), n4x, 1);

    dim3 gg(ND / 128, NTOK / 128);  // (8, 16)
    gemm_mma<0><<<gg, 256>>>(sp->xqh, sp->xql, sp->wqh, sp->wql, bq, sp->qm);
    gemm_mma<0><<<gg, 256>>>(sp->xkh, sp->xkl, sp->wkh, sp->wkl, bk, sp->km);
    gemm_mma<0><<<gg, 256>>>(sp->xvh, sp->xvl, sp->wvh, sp->wvl, bv, sp->vm);
    gemm_mma<1><<<gg, 256>>>(sp->xsh, sp->xsl, sp->w2h, sp->w2l, nullptr, sp->vvar);

    colsum_part<<<dim3(ND / 256, 8, NB), 256>>>(sp->vvar, sp->cpart);
    colsum_final<<<(NB * ND) / 256, 256>>>(sp->cpart, sp->csum);

    attn_kernel<<<dim3(NS / 64, NH, NB), 256, attn_smem>>>(
        sp->qm, sp->km, sp->vm, sp->vvar, sp->csum, tau, sp->ym, sp->T);

    split_bf16<<<n4x/256, 256>>>(sp->ym, BF2(sp->xyh), BF2(sp->xyl), n4x, 0);
    split_bf16<<<n4x/256, 256>>>(sp->T,  BF2(sp->xth), BF2(sp->xtl), n4x, 0);

    gemm_mma<0><<<gg, 256>>>(sp->xyh, sp->xyl, sp->woh, sp->wol, bo, out);
    gemm_mma<2><<<gg, 256>>>(sp->xth, sp->xtl, sp->o2h, sp->o2l, nullptr,
                             out + (size_t)NTOK * ND);
}

// round 10
// speedup vs baseline: 1.0037x; 1.0037x over previous
#include <cuda_runtime.h>
#include <cuda_bf16.h>
#include <cstdint>
#include <math.h>

#define NB 2
#define NS 1024
#define ND 1024
#define NH 16
#define NHD 64
#define NTOK (NB*NS)
#define EPSF 1e-6f
#define PADR 68
#define KS 20   // u32 stride of smem tile rows (conflict-free: g*20+t distinct mod 32)

// ---------------- scratch (static device memory; no allocs) ----------------
struct Scratch {
    float qm[NTOK*ND];
    float km[NTOK*ND];
    float vm[NTOK*ND];
    float vvar[NTOK*ND];
    float ym[NTOK*ND];
    float T[NTOK*ND];
    float cpart[NB*8*ND];
    float csum[NB*ND];
    // bf16 hi/lo splits of X operands
    __nv_bfloat16 xqh[NTOK*ND], xql[NTOK*ND];
    __nv_bfloat16 xkh[NTOK*ND], xkl[NTOK*ND];
    __nv_bfloat16 xvh[NTOK*ND], xvl[NTOK*ND];
    __nv_bfloat16 xsh[NTOK*ND], xsl[NTOK*ND];   // v_scale^2
    __nv_bfloat16 xyh[NTOK*ND], xyl[NTOK*ND];   // ym
    __nv_bfloat16 xth[NTOK*ND], xtl[NTOK*ND];   // T
    // bf16 hi/lo splits of W operands
    __nv_bfloat16 wqh[ND*ND], wql[ND*ND];
    __nv_bfloat16 wkh[ND*ND], wkl[ND*ND];
    __nv_bfloat16 wvh[ND*ND], wvl[ND*ND];
    __nv_bfloat16 w2h[ND*ND], w2l[ND*ND];       // Wv^2
    __nv_bfloat16 woh[ND*ND], wol[ND*ND];
    __nv_bfloat16 o2h[ND*ND], o2l[ND*ND];       // Wo^2
};
__device__ Scratch g_s;

static inline __nv_bfloat162* BF2(__nv_bfloat16* p) { return (__nv_bfloat162*)p; }

// ---------------- warp-level bf16 MMA (sm_80 baseline ISA) -----------------
__device__ __forceinline__ void mma_bf16(float* c, const uint32_t* a, const uint32_t* b) {
    asm volatile(
        "mma.sync.aligned.m16n8k16.row.col.f32.bf16.bf16.f32 "
        "{%0,%1,%2,%3}, {%4,%5,%6,%7}, {%8,%9}, {%0,%1,%2,%3};\n"
        : "+f"(c[0]), "+f"(c[1]), "+f"(c[2]), "+f"(c[3])
        : "r"(a[0]), "r"(a[1]), "r"(a[2]), "r"(a[3]), "r"(b[0]), "r"(b[1]));
}

// ---------------- fp32 -> bf16 hi/lo split (optionally squared) -------------
__global__ void split_bf16(const float* __restrict__ x,
                           __nv_bfloat162* __restrict__ hi,
                           __nv_bfloat162* __restrict__ lo,
                           int n4, int sq) {
    int i = blockIdx.x * blockDim.x + threadIdx.x;
    if (i >= n4) return;
    float4 v = ((const float4*)x)[i];
    if (sq) { v.x *= v.x; v.y *= v.y; v.z *= v.z; v.w *= v.w; }
    __nv_bfloat162 h0 = __floats2bfloat162_rn(v.x, v.y);
    __nv_bfloat162 h1 = __floats2bfloat162_rn(v.z, v.w);
    __nv_bfloat162 l0 = __floats2bfloat162_rn(v.x - __low2float(h0), v.y - __high2float(h0));
    __nv_bfloat162 l1 = __floats2bfloat162_rn(v.z - __low2float(h1), v.w - __high2float(h1));
    hi[i * 2]     = h0;
    hi[i * 2 + 1] = h1;
    lo[i * 2]     = l0;
    lo[i * 2 + 1] = l1;
}

// ---------------- split-bf16 NT GEMM on mma.sync ----------------------------
// Y[row,col] = f( sum_k X[row,k]*W[col,k] ), X=Xh+Xl, W=Wh+Wl (HH+HL+LH terms)
// MODE 0: +bias ; MODE 1: (sqrt(v)+eps)^2 ; MODE 2: sqrt(v)
template<int MODE>
__global__ void __launch_bounds__(256) gemm_mma(
    const __nv_bfloat16* __restrict__ Xh, const __nv_bfloat16* __restrict__ Xl,
    const __nv_bfloat16* __restrict__ Wh, const __nv_bfloat16* __restrict__ Wl,
    const float* __restrict__ bias, float* __restrict__ Y) {

    __shared__ uint32_t SH[4][128 * KS];    // Xh, Xl, Wh, Wl tiles (k32 chunk, paired bf16)

    const int tid = threadIdx.x;
    const int wid = tid >> 5, lane = tid & 31;
    const int g = lane >> 2, tig = lane & 3;          // mma fragment coords
    const int wm = wid & 1, wn = wid >> 1;            // 2x4 warp grid
    const int col0 = blockIdx.x * 128, row0 = blockIdx.y * 128;

    const __nv_bfloat16* srcs[4];
    srcs[0] = Xh + (size_t)row0 * ND;
    srcs[1] = Xl + (size_t)row0 * ND;
    srcs[2] = Wh + (size_t)col0 * ND;
    srcs[3] = Wl + (size_t)col0 * ND;

    float acc[4][4][4] = {};                          // [mi][ni][frag]

    for (int c = 0; c < 32; ++c) {                    // K chunks of 32
        const int k0 = c * 32;
        if (c) __syncthreads();
        #pragma unroll
        for (int a = 0; a < 4; ++a) {
            #pragma unroll
            for (int i = 0; i < 2; ++i) {
                int v = tid + i * 256;                // 0..511
                int row = v >> 2, quad = v & 3;
                uint4 val = *(const uint4*)(srcs[a] + (size_t)row * ND + k0 + quad * 8);
                *(uint4*)&SH[a][row * KS + quad * 4] = val;
            }
        }
        __syncthreads();

        #pragma unroll
        for (int s = 0; s < 2; ++s) {                 // two k16 steps
            const int s8 = s * 8;
            uint32_t ah[4][4], al[4][4], bh[4][2], bl[4][2];
            #pragma unroll
            for (int mi = 0; mi < 4; ++mi) {
                int r0 = (wm * 64 + mi * 16 + g) * KS + s8 + tig;
                int r1 = r0 + 8 * KS;
                ah[mi][0] = SH[0][r0];     ah[mi][1] = SH[0][r1];
                ah[mi][2] = SH[0][r0 + 4]; ah[mi][3] = SH[0][r1 + 4];
                al[mi][0] = SH[1][r0];     al[mi][1] = SH[1][r1];
                al[mi][2] = SH[1][r0 + 4]; al[mi][3] = SH[1][r1 + 4];
            }
            #pragma unroll
            for (int ni = 0; ni < 4; ++ni) {
                int n0 = (wn * 32 + ni * 8 + g) * KS + s8 + tig;
                bh[ni][0] = SH[2][n0]; bh[ni][1] = SH[2][n0 + 4];
                bl[ni][0] = SH[3][n0]; bl[ni][1] = SH[3][n0 + 4];
            }
            #pragma unroll
            for (int mi = 0; mi < 4; ++mi)
                #pragma unroll
                for (int ni = 0; ni < 4; ++ni) {
                    mma_bf16(acc[mi][ni], ah[mi], bh[ni]);
                    mma_bf16(acc[mi][ni], ah[mi], bl[ni]);
                    mma_bf16(acc[mi][ni], al[mi], bh[ni]);
                }
        }
    }

    // epilogue
    #pragma unroll
    for (int mi = 0; mi < 4; ++mi) {
        const int rA = row0 + wm * 64 + mi * 16 + g;
        #pragma unroll
        for (int ni = 0; ni < 4; ++ni) {
            const int cA = col0 + wn * 32 + ni * 8 + tig * 2;
            float v0 = acc[mi][ni][0], v1 = acc[mi][ni][1];
            float v2 = acc[mi][ni][2], v3 = acc[mi][ni][3];
            if (MODE == 0) {
                float b0 = bias[cA], b1 = bias[cA + 1];
                v0 += b0; v1 += b1; v2 += b0; v3 += b1;
            }
            if (MODE == 1) {
                float s;
                s = sqrtf(fmaxf(v0, 0.f)) + EPSF; v0 = s * s;
                s = sqrtf(fmaxf(v1, 0.f)) + EPSF; v1 = s * s;
                s = sqrtf(fmaxf(v2, 0.f)) + EPSF; v2 = s * s;
                s = sqrtf(fmaxf(v3, 0.f)) + EPSF; v3 = s * s;
            }
            if (MODE == 2) {
                v0 = sqrtf(fmaxf(v0, 0.f)); v1 = sqrtf(fmaxf(v1, 0.f));
                v2 = sqrtf(fmaxf(v2, 0.f)); v3 = sqrtf(fmaxf(v3, 0.f));
            }
            *(float2*)&Y[(size_t)rA * ND + cA]       = make_float2(v0, v1);
            *(float2*)&Y[(size_t)(rA + 8) * ND + cA] = make_float2(v2, v3);
        }
    }
}

// ---------------- column sums of vvar over S: csum[b][d] -------------------
__global__ void colsum_part(const float* __restrict__ vvar, float* __restrict__ cpart) {
    int d = blockIdx.x * 256 + threadIdx.x;
    int chunk = blockIdx.y;
    int b = blockIdx.z;
    const float* p = vvar + ((size_t)b * NS + chunk * 128) * ND + d;
    float s = 0.f;
    #pragma unroll 8
    for (int t = 0; t < 128; ++t) s += p[(size_t)t * ND];
    cpart[(b * 8 + chunk) * ND + d] = s;
}

__global__ void colsum_final(const float* __restrict__ cpart, float* __restrict__ csum) {
    int idx = blockIdx.x * 256 + threadIdx.x;
    int b = idx / ND, d = idx % ND;
    float s = 0.f;
    #pragma unroll
    for (int c = 0; c < 8; ++c) s += cpart[(b * 8 + c) * ND + d];
    csum[idx] = s;
}

// ---------------- fused distributional attention ---------------------------
#define ATTN_SMEM_FLOATS (6*64*PADR + 3*64 + 64*16)
__global__ void __launch_bounds__(256, 2) attn_kernel(
    const float* __restrict__ qm, const float* __restrict__ km,
    const float* __restrict__ vm, const float* __restrict__ vvar,
    const float* __restrict__ csum, const float* __restrict__ tau_p,
    float* __restrict__ ym, float* __restrict__ Tout) {

    extern __shared__ float smem[];
    float* QT  = smem;
    float* KT  = QT  + 64 * PADR;
    float* Vs  = KT  + 64 * PADR;
    float* VVs = Vs  + 64 * PADR;
    float* PT1 = VVs + 64 * PADR;
    float* PT2 = PT1 + 64 * PADR;
    float* rowmax = PT2 + 64 * PADR;
    float* rowz1  = rowmax + 64;
    float* rowz2  = rowz1 + 64;
    float* red    = rowz2 + 64;

    const int tid = threadIdx.x;
    const int tx = tid & 15, ty = tid >> 4;
    const int q0 = blockIdx.x * 64;
    const int h  = blockIdx.y;
    const int b  = blockIdx.z;

    const float tau   = tau_p[0];
    const float scl   = 1.0f / (8.0f * tau);
    const float s_var = (0.1f + EPSF) / 64.0f + EPSF;
    const float l_var = s_var / (tau * tau) + EPSF;
    const float cc    = rsqrtf(1.0f + 0.39269908169872414f * l_var);

    const size_t hoff = (size_t)h * NHD;
    const float* qbase = qm + ((size_t)b * NS + q0) * ND + hoff;

    for (int idx = tid; idx < 64 * 64; idx += 256) {
        int d = idx & 63, r = idx >> 6;
        QT[d * PADR + r] = qbase[(size_t)r * ND + d] * scl;
    }

    float lm[4] = {-INFINITY, -INFINITY, -INFINITY, -INFINITY};
    for (int kt = 0; kt < 16; ++kt) {
        __syncthreads();
        const float* kbase = km + ((size_t)b * NS + kt * 64) * ND + hoff;
        for (int idx = tid; idx < 64 * 64; idx += 256) {
            int d = idx & 63, r = idx >> 6;
            KT[d * PADR + r] = kbase[(size_t)r * ND + d];
        }
        __syncthreads();
        float sc[4][4] = {};
        #pragma unroll 8
        for (int d = 0; d < 64; ++d) {
            float4 qa = *(const float4*)&QT[d * PADR + ty * 4];
            float4 kb = *(const float4*)&KT[d * PADR + tx * 4];
            float av[4] = {qa.x, qa.y, qa.z, qa.w};
            float bv[4] = {kb.x, kb.y, kb.z, kb.w};
            #pragma unroll
            for (int i = 0; i < 4; ++i)
                #pragma unroll
                for (int j = 0; j < 4; ++j)
                    sc[i][j] = fmaf(av[i], bv[j], sc[i][j]);
        }
        #pragma unroll
        for (int i = 0; i < 4; ++i)
            #pragma unroll
            for (int j = 0; j < 4; ++j)
                lm[i] = fmaxf(lm[i], sc[i][j]);
    }
    __syncthreads();
    #pragma unroll
    for (int i = 0; i < 4; ++i) red[(ty * 4 + i) * 16 + tx] = lm[i];
    __syncthreads();
    if (tid < 64) {
        float m = red[tid * 16];
        #pragma unroll
        for (int t = 1; t < 16; ++t) m = fmaxf(m, red[tid * 16 + t]);
        rowmax[tid] = m;
    }
    __syncthreads();

    float mrow[4];
    #pragma unroll
    for (int i = 0; i < 4; ++i) mrow[i] = rowmax[ty * 4 + i];

    float acc1[4][4] = {}, acc2[4][4] = {}, acc3[4][4] = {}, acc4[4][4] = {};
    float z1l[4] = {}, z2l[4] = {};
    for (int kt = 0; kt < 16; ++kt) {
        __syncthreads();
        const float* kbase  = km   + ((size_t)b * NS + kt * 64) * ND + hoff;
        const float* vbase  = vm   + ((size_t)b * NS + kt * 64) * ND + hoff;
        const float* vvbase = vvar + ((size_t)b * NS + kt * 64) * ND + hoff;
        for (int idx = tid; idx < 64 * 64; idx += 256) {
            int d = idx & 63, r = idx >> 6;
            KT[d * PADR + r]  = kbase[(size_t)r * ND + d];
            Vs[r * PADR + d]  = vbase[(size_t)r * ND + d];
            VVs[r * PADR + d] = vvbase[(size_t)r * ND + d];
        }
        __syncthreads();

        float sc[4][4] = {};
        #pragma unroll 8
        for (int d = 0; d < 64; ++d) {
            float4 qa = *(const float4*)&QT[d * PADR + ty * 4];
            float4 kb = *(const float4*)&KT[d * PADR + tx * 4];
            float av[4] = {qa.x, qa.y, qa.z, qa.w};
            float bv[4] = {kb.x, kb.y, kb.z, kb.w};
            #pragma unroll
            for (int i = 0; i < 4; ++i)
                #pragma unroll
                for (int j = 0; j < 4; ++j)
                    sc[i][j] = fmaf(av[i], bv[j], sc[i][j]);
        }
        #pragma unroll
        for (int i = 0; i < 4; ++i) {
            #pragma unroll
            for (int j = 0; j < 4; ++j) {
                float dlt = sc[i][j] - mrow[i];
                float e1 = expf(dlt);
                float e2 = expf(cc * dlt);
                PT1[(tx * 4 + j) * PADR + ty * 4 + i] = e1;
                PT2[(tx * 4 + j) * PADR + ty * 4 + i] = e2;
                z1l[i] += e1;
                z2l[i] += e2;
            }
        }
        __syncthreads();

        #pragma unroll 4
        for (int t = 0; t < 64; ++t) {
            float4 p1 = *(const float4*)&PT1[t * PADR + ty * 4];
            float4 p2 = *(const float4*)&PT2[t * PADR + ty * 4];
            float4 vv = *(const float4*)&Vs[t * PADR + tx * 4];
            float4 wv = *(const float4*)&VVs[t * PADR + tx * 4];
            float p1a[4] = {p1.x, p1.y, p1.z, p1.w};
            float p2a[4] = {p2.x, p2.y, p2.z, p2.w};
            float va[4]  = {vv.x, vv.y, vv.z, vv.w};
            float wa[4]  = {wv.x, wv.y, wv.z, wv.w};
            #pragma unroll
            for (int i = 0; i < 4; ++i) {
                float p2s = p2a[i] * p2a[i];
                #pragma unroll
                for (int j = 0; j < 4; ++j) {
                    acc1[i][j] = fmaf(p1a[i], va[j], acc1[i][j]);
                    acc2[i][j] = fmaf(p2a[i], va[j], acc2[i][j]);
                    acc3[i][j] = fmaf(p2a[i], wa[j], acc3[i][j]);
                    acc4[i][j] = fmaf(p2s,   wa[j], acc4[i][j]);
                }
            }
        }
    }

    __syncthreads();
    #pragma unroll
    for (int i = 0; i < 4; ++i) red[(ty * 4 + i) * 16 + tx] = z1l[i];
    __syncthreads();
    if (tid < 64) {
        float s = 0.f;
        #pragma unroll
        for (int t = 0; t < 16; ++t) s += red[tid * 16 + t];
        rowz1[tid] = s;
    }
    __syncthreads();
    #pragma unroll
    for (int i = 0; i < 4; ++i) red[(ty * 4 + i) * 16 + tx] = z2l[i];
    __syncthreads();
    if (tid < 64) {
        float s = 0.f;
        #pragma unroll
        for (int t = 0; t < 16; ++t) s += red[tid * 16 + t];
        rowz2[tid] = s;
    }
    __syncthreads();

    const float Aconst = 1e-4f + EPSF;
    #pragma unroll
    for (int i = 0; i < 4; ++i) {
        int r = ty * 4 + i;
        float iZ1 = 1.0f / rowz1[r];
        float iZ2 = 1.0f / rowz2[r];
        float o1[4], o2[4];
        #pragma unroll
        for (int j = 0; j < 4; ++j) {
            int dc = tx * 4 + j;
            float ymu = acc1[i][j] * iZ1 + acc2[i][j] * iZ2;
            float yv  = Aconst * csum[b * ND + (int)hoff + dc]
                      + l_var * (acc3[i][j] * iZ2 - acc4[i][j] * iZ2 * iZ2);
            float ys = sqrtf(yv + EPSF) + EPSF;
            o1[j] = ymu;
            o2[j] = ys * ys;
        }
        size_t off = ((size_t)b * NS + q0 + r) * ND + hoff + tx * 4;
        *(float4*)&ym[off]   = make_float4(o1[0], o1[1], o1[2], o1[3]);
        *(float4*)&Tout[off] = make_float4(o2[0], o2[1], o2[2], o2[3]);
    }
}

// ---------------- launch ----------------------------------------------------
extern "C" void kernel_launch(void* const* d_in, const int* in_sizes, int n_in,
                              void* d_out, int out_size) {
    (void)in_sizes; (void)n_in; (void)out_size;
    const float* q_loc   = (const float*)d_in[0];
    const float* k_loc   = (const float*)d_in[2];
    const float* v_loc   = (const float*)d_in[4];
    const float* v_scale = (const float*)d_in[5];
    const float* Wq = (const float*)d_in[6];
    const float* bq = (const float*)d_in[7];
    const float* Wk = (const float*)d_in[8];
    const float* bk = (const float*)d_in[9];
    const float* Wv = (const float*)d_in[10];
    const float* bv = (const float*)d_in[11];
    const float* Wo = (const float*)d_in[12];
    const float* bo = (const float*)d_in[13];
    const float* tau = (const float*)d_in[14];
    float* out = (float*)d_out;

    Scratch* sp = nullptr;
    cudaGetSymbolAddress((void**)&sp, g_s);

    const int attn_smem = ATTN_SMEM_FLOATS * (int)sizeof(float);
    cudaFuncSetAttribute(attn_kernel, cudaFuncAttributeMaxDynamicSharedMemorySize, attn_smem);

    const int n4x = NTOK * ND / 4, n4w = ND * ND / 4;
    // W splits
    split_bf16<<<n4w/256, 256>>>(Wq, BF2(sp->wqh), BF2(sp->wql), n4w, 0);
    split_bf16<<<n4w/256, 256>>>(Wk, BF2(sp->wkh), BF2(sp->wkl), n4w, 0);
    split_bf16<<<n4w/256, 256>>>(Wv, BF2(sp->wvh), BF2(sp->wvl), n4w, 0);
    split_bf16<<<n4w/256, 256>>>(Wv, BF2(sp->w2h), BF2(sp->w2l), n4w, 1);
    split_bf16<<<n4w/256, 256>>>(Wo, BF2(sp->woh), BF2(sp->wol), n4w, 0);
    split_bf16<<<n4w/256, 256>>>(Wo, BF2(sp->o2h), BF2(sp->o2l), n4w, 1);
    // X splits
    split_bf16<<<n4x/256, 256>>>(q_loc,   BF2(sp->xqh), BF2(sp->xql), n4x, 0);
    split_bf16<<<n4x/256, 256>>>(k_loc,   BF2(sp->xkh), BF2(sp->xkl), n4x, 0);
    split_bf16<<<n4x/256, 256>>>(v_loc,   BF2(sp->xvh), BF2(sp->xvl), n4x, 0);
    split_bf16<<<n4x/256, 256>>>(v_scale, BF2(sp->xsh), BF2(sp->xsl), n4x, 1);

    dim3 gg(ND / 128, NTOK / 128);  // (8, 16)
    gemm_mma<0><<<gg, 256>>>(sp->xqh, sp->xql, sp->wqh, sp->wql, bq, sp->qm);
    gemm_mma<0><<<gg, 256>>>(sp->xkh, sp->xkl, sp->wkh, sp->wkl, bk, sp->km);
    gemm_mma<0><<<gg, 256>>>(sp->xvh, sp->xvl, sp->wvh, sp->wvl, bv, sp->vm);
    gemm_mma<1><<<gg, 256>>>(sp->xsh, sp->xsl, sp->w2h, sp->w2l, nullptr, sp->vvar);

    colsum_part<<<dim3(ND / 256, 8, NB), 256>>>(sp->vvar, sp->cpart);
    colsum_final<<<(NB * ND) / 256, 256>>>(sp->cpart, sp->csum);

    attn_kernel<<<dim3(NS / 64, NH, NB), 256, attn_smem>>>(
        sp->qm, sp->km, sp->vm, sp->vvar, sp->csum, tau, sp->ym, sp->T);

    split_bf16<<<n4x/256, 256>>>(sp->ym, BF2(sp->xyh), BF2(sp->xyl), n4x, 0);
    split_bf16<<<n4x/256, 256>>>(sp->T,  BF2(sp->xth), BF2(sp->xtl), n4x, 0);

    gemm_mma<0><<<gg, 256>>>(sp->xyh, sp->xyl, sp->woh, sp->wol, bo, out);
    gemm_mma<2><<<gg, 256>>>(sp->xth, sp->xtl, sp->o2h, sp->o2l, nullptr,
                             out + (size_t)NTOK * ND);
}